// round 1
// baseline (speedup 1.0000x reference)
#include <cuda_runtime.h>
#include <math.h>

// Problem dims (fixed by the reference)
#define PDIM 4096
#define BDIM 256
#define RSPLIT 128          // row splits for the matvec (parallelism)
#define ROWS_PER (PDIM / RSPLIT)   // 32 rows per partial block
#define CBLK 1024           // columns per block in K1 (256 threads * float4)

// Scratch: partial sums of the lateral matvec. 128 * 4096 * 4B = 2 MB.
__device__ float g_partial[RSPLIT * PDIM];
__device__ float g_lateral[PDIM];

// K1: partial matvec  partial[r][j] = sum_{i in rows(r)} pop[i] * W[i*P + j]
// Grid: (PDIM/CBLK, RSPLIT) = (4, 128). Block: 256 threads, 4 cols/thread.
__global__ __launch_bounds__(256) void matvec_partial_kernel(
    const float* __restrict__ W, const float* __restrict__ pop)
{
    const int col = blockIdx.x * CBLK + threadIdx.x * 4;
    const int r   = blockIdx.y;
    const int i0  = r * ROWS_PER;

    float4 acc = make_float4(0.f, 0.f, 0.f, 0.f);
    #pragma unroll 8
    for (int i = i0; i < i0 + ROWS_PER; ++i) {
        const float p  = __ldg(&pop[i]);
        const float4 w = *reinterpret_cast<const float4*>(
            &W[(size_t)i * PDIM + col]);
        acc.x = fmaf(p, w.x, acc.x);
        acc.y = fmaf(p, w.y, acc.y);
        acc.z = fmaf(p, w.z, acc.z);
        acc.w = fmaf(p, w.w, acc.w);
    }
    *reinterpret_cast<float4*>(&g_partial[r * PDIM + col]) = acc;
}

// K2: deterministic reduction over the RSPLIT partials + diagonal correction.
// One thread per column. 4096 threads total.
__global__ __launch_bounds__(256) void reduce_lateral_kernel(
    const float* __restrict__ W, const float* __restrict__ pop)
{
    const int j = blockIdx.x * blockDim.x + threadIdx.x;
    float s = 0.f;
    #pragma unroll 16
    for (int r = 0; r < RSPLIT; ++r)
        s += g_partial[r * PDIM + j];
    // reference zeroes the diagonal BEFORE the matvec; subtracting the
    // diagonal term afterwards is mathematically identical (1-ulp class diff)
    s -= pop[j] * W[(size_t)j * PDIM + j];
    g_lateral[j] = s;
}

// K3: fused LIF step + hard spike. Forward value of the straight-through
// estimator is exactly the hard threshold result (soft terms cancel).
__global__ __launch_bounds__(256) void spike_kernel(
    const float* __restrict__ ext, const float* __restrict__ v,
    const float* __restrict__ thr, float* __restrict__ out)
{
    // exp(-DT/TAU_MEM) = exp(-0.1), fp32-rounded
    const float decay = 0.90483741803595957f;

    const int idx = (blockIdx.x * blockDim.x + threadIdx.x) * 4;  // element idx
    const int j   = idx & (PDIM - 1);                             // column base

    const float4 e  = *reinterpret_cast<const float4*>(&ext[idx]);
    const float4 vv = *reinterpret_cast<const float4*>(&v[idx]);
    const float4 t  = *reinterpret_cast<const float4*>(&thr[idx]);
    const float4 l  = *reinterpret_cast<const float4*>(&g_lateral[j]);

    float4 o;
    o.x = (fmaf(decay, vv.x, e.x - l.x) > t.x) ? 1.f : 0.f;
    o.y = (fmaf(decay, vv.y, e.y - l.y) > t.y) ? 1.f : 0.f;
    o.z = (fmaf(decay, vv.z, e.z - l.z) > t.z) ? 1.f : 0.f;
    o.w = (fmaf(decay, vv.w, e.w - l.w) > t.w) ? 1.f : 0.f;

    *reinterpret_cast<float4*>(&out[idx]) = o;
}

extern "C" void kernel_launch(void* const* d_in, const int* in_sizes, int n_in,
                              void* d_out, int out_size)
{
    const float* ext = (const float*)d_in[0];  // external_input [B, P]
    const float* W   = (const float*)d_in[1];  // lateral_weights [P, P]
    const float* pop = (const float*)d_in[2];  // population_activity [P]
    const float* v   = (const float*)d_in[3];  // v [B, P]
    const float* thr = (const float*)d_in[4];  // threshold [B, P]
    float* out = (float*)d_out;                // spikes [B, P]

    dim3 g1(PDIM / CBLK, RSPLIT);              // (4, 128) = 512 blocks
    matvec_partial_kernel<<<g1, 256>>>(W, pop);

    reduce_lateral_kernel<<<PDIM / 256, 256>>>(W, pop);

    const int n4 = BDIM * PDIM / 4;            // 262144 float4 work items
    spike_kernel<<<n4 / 256, 256>>>(ext, v, thr, out);
}